// round 11
// baseline (speedup 1.0000x reference)
#include <cuda_runtime.h>
#include <cuda_bf16.h>

// Sliding-window unfold: out[b, i, j] = x[b, i + j]
//   x:   [B=128, L=8192]  float32
//   out: [B=128, NWIN=8162, W=31] float32
//
// R10: R9 compute (skewed-smem scalar LDS, 8 dense __stcs STG.128 quads,
// 32 outputs/thread/tile) + software pipeline: each block runs NT=4 tiles
// with double-buffered smem; next tile's span is LDG'd into registers
// before computing the current tile, STS'd after, hiding staging latency.

static constexpr unsigned Bv    = 128u;
static constexpr unsigned Lv    = 8192u;
static constexpr unsigned Wv    = 31u;
static constexpr unsigned Rv    = Wv / 2u;           // 15
static constexpr unsigned NWIN  = Lv - 2u * Rv;      // 8162
static constexpr unsigned ROW   = NWIN * Wv;         // 253022
static constexpr unsigned TOTAL = Bv * ROW;          // 32,386,816
static constexpr unsigned OPB   = 8192u;             // outputs per tile (256 thr x 32)
static constexpr unsigned QSTEP = 1024u;             // = 33*31 + 1
static constexpr unsigned NQ    = 8u;                // quads per thread per tile
static constexpr unsigned NTILES = (TOTAL + OPB - 1u) / OPB;   // 3954
static constexpr unsigned NT    = 4u;                // tiles per block
static constexpr unsigned NBLK  = (NTILES + NT - 1u) / NT;     // 989

static constexpr unsigned SPAN  = 304u;              // staged floats (max src <= i0+294)
static constexpr unsigned SPHYS = SPAN + SPAN / 32u + 1u;  // 314

__device__ __forceinline__ void stage_regs(const float* __restrict__ x,
                                           unsigned tile, unsigned t,
                                           float& r0, float& r1) {
    unsigned o0   = tile * OPB;
    unsigned b0   = o0 / ROW;                        // magic-multiply
    unsigned rem0 = o0 - b0 * ROW;
    unsigned i0   = rem0 / Wv;
    const float* __restrict__ xr = x + (size_t)b0 * Lv;
    unsigned g0 = i0 + t;
    r0 = xr[g0 < Lv ? g0 : (Lv - 1u)];
    if (t + 256u < SPAN) {
        unsigned g1 = i0 + t + 256u;
        r1 = xr[g1 < Lv ? g1 : (Lv - 1u)];
    }
}

__global__ void __launch_bounds__(256)
WindowAlignmentLayer_65876208386448_kernel(const float* __restrict__ x,
                                           float* __restrict__ out) {
    __shared__ float sx[2][SPHYS];

    const unsigned t     = threadIdx.x;
    const unsigned tbase = blockIdx.x * NT;

    // Prologue: stage tile tbase into buffer 0.
    float r0 = 0.f, r1 = 0.f;
    stage_regs(x, tbase, t, r0, r1);
    sx[0][t + (t >> 5)] = r0;
    if (t + 256u < SPAN) { unsigned c = t + 256u; sx[0][c + (c >> 5)] = r1; }
    __syncthreads();

    for (unsigned k = 0; k < NT; ++k) {
        const unsigned tile = tbase + k;
        if (tile >= NTILES) break;                   // block-uniform
        const unsigned buf = k & 1u;

        // Prefetch next tile's span into registers (latency hidden by compute).
        const bool havenext = (k + 1u < NT) && (tile + 1u < NTILES);
        float n0 = 0.f, n1 = 0.f;
        if (havenext) stage_regs(x, tile + 1u, t, n0, n1);

        // ---- compute tile ----
        const unsigned o0   = tile * OPB;
        const unsigned b0   = o0 / ROW;
        const unsigned rem0 = o0 - b0 * ROW;
        const bool fast = (rem0 + OPB <= ROW) && (o0 + OPB <= TOTAL);

        if (fast) {
            const unsigned i0  = rem0 / Wv;
            const unsigned rem = rem0 + t * 4u;
            unsigned iq = rem / Wv;                  // magic-multiply
            unsigned jq = rem - iq * Wv;

            float* __restrict__ ob = out + (o0 + t * 4u);
#pragma unroll
            for (unsigned q = 0; q < NQ; ++q) {
                const unsigned sA = iq + jq - i0;    // local src base (run A)
                const unsigned m  = Wv - jq;         // k >= m -> window wrap (-30)

                float v[4];
#pragma unroll
                for (unsigned kk = 0; kk < 4u; ++kk) {
                    unsigned src = sA + kk - ((kk >= m) ? (Wv - 1u) : 0u);
                    v[kk] = sx[buf][src + (src >> 5)];
                }
                float4 q4;
                q4.x = v[0]; q4.y = v[1]; q4.z = v[2]; q4.w = v[3];
                __stcs(reinterpret_cast<float4*>(ob + q * QSTEP), q4);

                // advance (i,j) by +1024 flat outputs: i += 33, j += 1 (wrap)
                jq += 1u; iq += 33u;
                if (jq == Wv) { jq = 0u; iq += 1u; }
            }
        } else {
            // Cold: tile straddles a batch row, or partial tail (~130 tiles).
            for (unsigned kk = 0; kk < 32u; ++kk) {
                unsigned o = o0 + t + kk * 256u;     // coalesced scalar stores
                if (o < TOTAL) {
                    unsigned b   = o / ROW;
                    unsigned rem = o - b * ROW;
                    unsigned i   = rem / Wv;
                    unsigned j   = rem - i * Wv;
                    out[o] = __ldg(x + (size_t)b * Lv + (i + j));
                }
            }
        }

        // Commit prefetched tile into the other buffer; one sync per tile.
        if (havenext) {
            const unsigned ob2 = buf ^ 1u;
            sx[ob2][t + (t >> 5)] = n0;
            if (t + 256u < SPAN) { unsigned c = t + 256u; sx[ob2][c + (c >> 5)] = n1; }
        }
        __syncthreads();
    }
}

extern "C" void kernel_launch(void* const* d_in, const int* in_sizes, int n_in,
                              void* d_out, int out_size) {
    (void)in_sizes; (void)n_in; (void)out_size;
    const float* x   = (const float*)d_in[0];
    float*       out = (float*)d_out;

    WindowAlignmentLayer_65876208386448_kernel<<<NBLK, 256>>>(x, out);
}